// round 3
// baseline (speedup 1.0000x reference)
#include <cuda_runtime.h>
#include <cuda_bf16.h>

// Problem: feature [N, C] fp32, label [N] int32 (JAX demotes int64 w/o x64).
// loss = 2 - 2*(sum_i feature[i, label[i]] / 64) / N  = 2 - sum / (32*N)

#define TPB 256
#define MAX_BLOCKS 1024

__device__ float g_partials[MAX_BLOCKS];

__global__ void center_gather_reduce(const float* __restrict__ feature,
                                     const int* __restrict__ label,
                                     int n, int c) {
    int i = blockIdx.x * TPB + threadIdx.x;
    float v = 0.0f;
    if (i < n) {
        int col = label[i];
        if (col >= 0 && col < c)  // defensive: wrong value -> rel_err, not fault
            v = __ldg(&feature[(long long)i * c + col]);
    }
    // warp reduce
    #pragma unroll
    for (int off = 16; off > 0; off >>= 1)
        v += __shfl_xor_sync(0xFFFFFFFFu, v, off);

    __shared__ float warp_sums[TPB / 32];
    int lane = threadIdx.x & 31;
    int wid  = threadIdx.x >> 5;
    if (lane == 0) warp_sums[wid] = v;
    __syncthreads();

    if (wid == 0) {
        float s = (lane < TPB / 32) ? warp_sums[lane] : 0.0f;
        #pragma unroll
        for (int off = 4; off > 0; off >>= 1)
            s += __shfl_xor_sync(0xFFFFFFFFu, s, off);
        if (lane == 0) g_partials[blockIdx.x] = s;
    }
}

__global__ void center_finalize(float* __restrict__ out, int nblocks, float inv_denom) {
    float v = 0.0f;
    for (int i = threadIdx.x; i < nblocks; i += TPB)
        v += g_partials[i];
    #pragma unroll
    for (int off = 16; off > 0; off >>= 1)
        v += __shfl_xor_sync(0xFFFFFFFFu, v, off);

    __shared__ float warp_sums[TPB / 32];
    int lane = threadIdx.x & 31;
    int wid  = threadIdx.x >> 5;
    if (lane == 0) warp_sums[wid] = v;
    __syncthreads();

    if (wid == 0) {
        float s = (lane < TPB / 32) ? warp_sums[lane] : 0.0f;
        #pragma unroll
        for (int off = 4; off > 0; off >>= 1)
            s += __shfl_xor_sync(0xFFFFFFFFu, s, off);
        if (lane == 0)
            out[0] = 2.0f - s * inv_denom;
    }
}

extern "C" void kernel_launch(void* const* d_in, const int* in_sizes, int n_in,
                              void* d_out, int out_size) {
    const float* feature = (const float*)d_in[0];
    const int*   label   = (const int*)d_in[1];
    float*       out     = (float*)d_out;

    int n = in_sizes[1];                 // 8192
    int c = (int)(in_sizes[0] / n);      // 10000

    int nblocks = (n + TPB - 1) / TPB;   // 32
    if (nblocks > MAX_BLOCKS) nblocks = MAX_BLOCKS;

    float inv_denom = 1.0f / (32.0f * (float)n);

    center_gather_reduce<<<nblocks, TPB>>>(feature, label, n, c);
    center_finalize<<<1, TPB>>>(out, nblocks, inv_denom);
}

// round 4
// speedup vs baseline: 1.3237x; 1.3237x over previous
#include <cuda_runtime.h>
#include <cuda_bf16.h>

// Problem: feature [N, C] fp32, label [N] int32.
// loss = 2 - 2*(sum_i feature[i, label[i]] / 64) / N  = 2 - sum / (32*N)
// Single fused kernel: gather + block reduce + last-block-done final reduce.

#define TPB 256
#define MAX_BLOCKS 1024

__device__ float g_partials[MAX_BLOCKS];
__device__ unsigned int g_ticket = 0;   // reset to 0 by last block -> graph-replayable

__global__ void center_fused(const float* __restrict__ feature,
                             const int* __restrict__ label,
                             int n, int c, float inv_denom,
                             float* __restrict__ out) {
    int i = blockIdx.x * TPB + threadIdx.x;
    float v = 0.0f;
    if (i < n) {
        int col = label[i];
        if (col >= 0 && col < c)
            v = __ldg(&feature[(long long)i * c + col]);
    }

    // block reduce
    #pragma unroll
    for (int off = 16; off > 0; off >>= 1)
        v += __shfl_xor_sync(0xFFFFFFFFu, v, off);

    __shared__ float warp_sums[TPB / 32];
    int lane = threadIdx.x & 31;
    int wid  = threadIdx.x >> 5;
    if (lane == 0) warp_sums[wid] = v;
    __syncthreads();

    if (wid == 0) {
        float s = (lane < TPB / 32) ? warp_sums[lane] : 0.0f;
        #pragma unroll
        for (int off = 4; off > 0; off >>= 1)
            s += __shfl_xor_sync(0xFFFFFFFFu, s, off);
        if (lane == 0) g_partials[blockIdx.x] = s;
    }

    // make partial visible before taking a ticket
    __threadfence();

    __shared__ int is_last;
    if (threadIdx.x == 0) {
        unsigned int old = atomicAdd(&g_ticket, 1u);
        is_last = (old == gridDim.x - 1u);
    }
    __syncthreads();

    if (is_last && wid == 0) {
        // gridDim.x <= 32 for this shape; loop handles the general case
        float s = 0.0f;
        for (unsigned int j = lane; j < gridDim.x; j += 32)
            s += g_partials[j];
        #pragma unroll
        for (int off = 16; off > 0; off >>= 1)
            s += __shfl_xor_sync(0xFFFFFFFFu, s, off);
        if (lane == 0) {
            out[0] = 2.0f - s * inv_denom;
            g_ticket = 0;  // reset for next graph replay
        }
    }
}

extern "C" void kernel_launch(void* const* d_in, const int* in_sizes, int n_in,
                              void* d_out, int out_size) {
    const float* feature = (const float*)d_in[0];
    const int*   label   = (const int*)d_in[1];
    float*       out     = (float*)d_out;

    int n = in_sizes[1];              // 8192
    int c = (int)(in_sizes[0] / n);   // 10000

    int nblocks = (n + TPB - 1) / TPB;   // 32
    if (nblocks > MAX_BLOCKS) nblocks = MAX_BLOCKS;

    float inv_denom = 1.0f / (32.0f * (float)n);

    center_fused<<<nblocks, TPB>>>(feature, label, n, c, inv_denom, out);
}